// round 2
// baseline (speedup 1.0000x reference)
#include <cuda_runtime.h>
#include <math.h>

// Problem constants
#define NB 16      // batch
#define MD 128     // M (x spatial)
#define ND 128     // N (y spatial)
#define DD 128     // d_model
#define NMODES 32
#define C2 64      // 2*NMODES (re/im interleaved as separate "c" rows)
#define HH 512     // FFN hidden

// ---------------- scratch (device globals; no runtime allocation) ----------------
__device__ float g_F[C2 * 128];           // forward DFT rows: [c][y], c=2k+ri
__device__ float g_Binv[128 * C2];        // inverse DFT: [y][c]
__device__ float g_Wy[NMODES * 256 * 256];// packed complex-mix matrices, y-axis
__device__ float g_Wx[NMODES * 256 * 256];// packed complex-mix matrices, x-axis
__device__ float g_xf[NB * MD * C2 * DD]; // forward transform output [batch][c][d]
__device__ float g_md[NB * MD * C2 * DD]; // mixed modes            [batch][c][d]
__device__ float g_h[NB * MD * ND * DD];  // fourier-layer output (xx + xy), [b,m,n,d]

// ---------------- DFT matrix construction ----------------
// rfft ortho:  X[k] = (1/sqrt(n)) sum_y x[y] e^{-2pi i k y / n}
//   F[2k][y]   =  cos(2pi k y/128)/sqrt(128)
//   F[2k+1][y] = -sin(2pi k y/128)/sqrt(128)
// irfft ortho (only bins k<32 nonzero, DC imag ignored by c2r):
//   Binv[y][2k]   = c_k cos(2pi k y/128)/sqrt(128),  c_0=1, c_k=2 (k>=1)
//   Binv[y][2k+1] = -c_k sin(...)/sqrt(128), except Binv[y][1] = 0 (DC imag ignored)
__global__ void build_dft_k() {
    int idx = blockIdx.x * 256 + threadIdx.x;
    const double invs = 0.08838834764831845;  // 1/sqrt(128)
    if (idx < C2 * 128) {
        int c = idx >> 7, y = idx & 127;
        int k = c >> 1;
        int t = (k * y) & 127;
        double s, co;
        sincospi((double)t / 64.0, &s, &co);
        g_F[idx] = (float)(((c & 1) == 0 ? co : -s) * invs);
    } else if (idx < 2 * C2 * 128) {
        int j = idx - C2 * 128;
        int y = j >> 6, c = j & 63;
        int k = c >> 1;
        int t = (k * y) & 127;
        double s, co;
        sincospi((double)t / 64.0, &s, &co);
        double sc = (k == 0 ? 1.0 : 2.0) * invs;
        float v;
        if ((c & 1) == 0) v = (float)(co * sc);
        else              v = (k == 0) ? 0.0f : (float)(-s * sc);
        g_Binv[y * 64 + c] = v;
    }
}

// ---------------- weight repack ----------------
// fw: [i][o][k][2]. Build Wbig[k] (256x256):
//   rows = (ri, i), cols = (ro, o):  [[Wr, Wi], [-Wi, Wr]]
__global__ void repack_k(const float* __restrict__ fw, int which) {
    float* W = which ? g_Wx : g_Wy;
    int idx = blockIdx.x * 256 + threadIdx.x;
    if (idx >= NMODES * DD * DD) return;
    int k = idx >> 14;
    int d = (idx >> 7) & 127;
    int o = idx & 127;
    float wr = fw[((d * DD + o) * NMODES + k) * 2 + 0];
    float wi = fw[((d * DD + o) * NMODES + k) * 2 + 1];
    float* Wk = W + k * 65536;
    Wk[d * 256 + o]               = wr;
    Wk[d * 256 + 128 + o]         = wi;
    Wk[(128 + d) * 256 + o]       = -wi;
    Wk[(128 + d) * 256 + 128 + o] = wr;
}

// ---------------- forward DFT (batched GEMM 64x128x128) ----------------
// mode 0 (y-axis): batch = b*128+m, A base = batch*16384, row stride(y) = 128
// mode 1 (x-axis): batch = b*128+n, A base = b*2097152 + n*128, row stride(m) = 16384
__global__ void __launch_bounds__(256) fwd_k(const float* __restrict__ x, int mode) {
    __shared__ float F_s[64 * 128];   // 32 KB
    __shared__ float X_s[32 * 128];   // 16 KB
    int tid = threadIdx.x;
    int batch = blockIdx.x;
    int aStride, base;
    if (mode == 0) { base = batch * 16384; aStride = 128; }
    else { int b = batch >> 7, n = batch & 127; base = b * 2097152 + n * 128; aStride = 16384; }
    const float* A = x + base;

    for (int i = tid; i < 64 * 128; i += 256) F_s[i] = g_F[i];

    int dgrp = tid & 31;        // d0 = dgrp*4
    int cgrp = tid >> 5;        // c0 = cgrp*8
    int c0 = cgrp * 8;
    float acc[8][4];
#pragma unroll
    for (int a = 0; a < 8; a++)
#pragma unroll
        for (int b = 0; b < 4; b++) acc[a][b] = 0.f;

    for (int y0 = 0; y0 < 128; y0 += 32) {
        __syncthreads();
        for (int i = tid; i < 32 * 32; i += 256) {
            int row = i >> 5, c4 = i & 31;
            ((float4*)X_s)[row * 32 + c4] =
                *((const float4*)(A + (y0 + row) * aStride + c4 * 4));
        }
        __syncthreads();
#pragma unroll 8
        for (int yy = 0; yy < 32; yy++) {
            float4 xv = ((const float4*)X_s)[yy * 32 + dgrp];
#pragma unroll
            for (int cc = 0; cc < 8; cc++) {
                float f = F_s[(c0 + cc) * 128 + y0 + yy];
                acc[cc][0] += f * xv.x;
                acc[cc][1] += f * xv.y;
                acc[cc][2] += f * xv.z;
                acc[cc][3] += f * xv.w;
            }
        }
    }
    float* O = g_xf + batch * 8192;
#pragma unroll
    for (int cc = 0; cc < 8; cc++) {
        ((float4*)O)[(c0 + cc) * 32 + dgrp] =
            make_float4(acc[cc][0], acc[cc][1], acc[cc][2], acc[cc][3]);
    }
}

// ---------------- mode mixing (per-mode GEMM 2048x256x256) ----------------
// grid: (colTiles=4, rowTiles=32, modes=32); block 256; tile 64x64, micro 4x4
__global__ void __launch_bounds__(256) mix_k(int which) {
    __shared__ float A_s[64 * 65];  // padded
    __shared__ float B_s[64 * 64];
    const float* W = which ? g_Wx : g_Wy;
    int tid = threadIdx.x;
    int colBase = blockIdx.x * 64;
    int rowBase = blockIdx.y * 64;
    int k = blockIdx.z;
    const float* Wk = W + k * 65536;
    int tx = tid & 15, ty = tid >> 4;
    float acc[4][4];
#pragma unroll
    for (int a = 0; a < 4; a++)
#pragma unroll
        for (int b = 0; b < 4; b++) acc[a][b] = 0.f;

    for (int kc0 = 0; kc0 < 256; kc0 += 64) {
        __syncthreads();
        for (int i = tid; i < 4096; i += 256) {
            int r = i >> 6, c = i & 63;
            A_s[r * 65 + c] = g_xf[(rowBase + r) * 8192 + k * 256 + kc0 + c];
            B_s[r * 64 + c] = Wk[(kc0 + r) * 256 + colBase + c];
        }
        __syncthreads();
#pragma unroll 8
        for (int kk = 0; kk < 64; kk++) {
            float4 bv = ((const float4*)B_s)[kk * 16 + tx];
            float a0 = A_s[(ty * 4 + 0) * 65 + kk];
            float a1 = A_s[(ty * 4 + 1) * 65 + kk];
            float a2 = A_s[(ty * 4 + 2) * 65 + kk];
            float a3 = A_s[(ty * 4 + 3) * 65 + kk];
            acc[0][0] += a0 * bv.x; acc[0][1] += a0 * bv.y; acc[0][2] += a0 * bv.z; acc[0][3] += a0 * bv.w;
            acc[1][0] += a1 * bv.x; acc[1][1] += a1 * bv.y; acc[1][2] += a1 * bv.z; acc[1][3] += a1 * bv.w;
            acc[2][0] += a2 * bv.x; acc[2][1] += a2 * bv.y; acc[2][2] += a2 * bv.z; acc[2][3] += a2 * bv.w;
            acc[3][0] += a3 * bv.x; acc[3][1] += a3 * bv.y; acc[3][2] += a3 * bv.z; acc[3][3] += a3 * bv.w;
        }
    }
#pragma unroll
    for (int j = 0; j < 4; j++) {
        float4* mp = (float4*)(g_md + (rowBase + ty * 4 + j) * 8192 + k * 256 + colBase);
        mp[tx] = make_float4(acc[j][0], acc[j][1], acc[j][2], acc[j][3]);
    }
}

// ---------------- inverse DFT + write/accumulate (batched GEMM 128x128x64) ----------------
// mode 0: out = g_h, base = batch*16384, stride(y)=128, plain write
// mode 1: accumulate into g_h at base = b*2097152 + n*128, stride(y=m)=16384
__global__ void __launch_bounds__(256) inv_k(int mode) {
    __shared__ float Bi_s[128 * 33];  // padded chunk [128][32]
    __shared__ float M_s[32 * 128];
    int tid = threadIdx.x;
    int batch = blockIdx.x;
    int base, ostride;
    if (mode == 0) { base = batch * 16384; ostride = 128; }
    else { int b = batch >> 7, n = batch & 127; base = b * 2097152 + n * 128; ostride = 16384; }
    int tx = tid & 15, ty = tid >> 4;
    int o0 = tx * 8, y0 = ty * 8;
    float acc[8][8];
#pragma unroll
    for (int a = 0; a < 8; a++)
#pragma unroll
        for (int b = 0; b < 8; b++) acc[a][b] = 0.f;

    for (int kc0 = 0; kc0 < 64; kc0 += 32) {
        __syncthreads();
        for (int i = tid; i < 128 * 32; i += 256) {
            int y = i >> 5, c = i & 31;
            Bi_s[y * 33 + c] = g_Binv[y * 64 + kc0 + c];
        }
        for (int i = tid; i < 32 * 128; i += 256) {
            int r = i >> 7, o = i & 127;
            M_s[i] = g_md[batch * 8192 + (kc0 + r) * 128 + o];
        }
        __syncthreads();
#pragma unroll 4
        for (int kk = 0; kk < 32; kk++) {
            float a[8];
#pragma unroll
            for (int j = 0; j < 8; j++) a[j] = Bi_s[(y0 + j) * 33 + kk];
            float4 b0 = ((const float4*)M_s)[kk * 32 + tx * 2];
            float4 b1 = ((const float4*)M_s)[kk * 32 + tx * 2 + 1];
#pragma unroll
            for (int j = 0; j < 8; j++) {
                acc[j][0] += a[j] * b0.x; acc[j][1] += a[j] * b0.y;
                acc[j][2] += a[j] * b0.z; acc[j][3] += a[j] * b0.w;
                acc[j][4] += a[j] * b1.x; acc[j][5] += a[j] * b1.y;
                acc[j][6] += a[j] * b1.z; acc[j][7] += a[j] * b1.w;
            }
        }
    }
#pragma unroll
    for (int j = 0; j < 8; j++) {
        float* p = g_h + base + (y0 + j) * ostride + o0;
        float4 v0 = make_float4(acc[j][0], acc[j][1], acc[j][2], acc[j][3]);
        float4 v1 = make_float4(acc[j][4], acc[j][5], acc[j][6], acc[j][7]);
        if (mode == 1) {
            float4 o0v = *((float4*)p);
            float4 o1v = *((float4*)(p + 4));
            v0.x += o0v.x; v0.y += o0v.y; v0.z += o0v.z; v0.w += o0v.w;
            v1.x += o1v.x; v1.y += o1v.y; v1.z += o1v.z; v1.w += o1v.w;
        }
        *((float4*)p) = v0;
        *((float4*)(p + 4)) = v1;
    }
}

// ---------------- fused FFN: out = relu(h @ w1 + b1) @ w2 + b2 ----------------
// 64-row tile per block, H chunked by 64, hidden never hits global memory.
#define FFN_H_S   (64 * 129)
#define FFN_HID_S (64 * 65)
#define FFN_WBUF  (128 * 64)
#define FFN_SMEM  ((FFN_H_S + FFN_HID_S + FFN_WBUF) * 4)

__global__ void __launch_bounds__(256) ffn_k(const float* __restrict__ w1,
                                             const float* __restrict__ b1,
                                             const float* __restrict__ w2,
                                             const float* __restrict__ b2,
                                             float* __restrict__ out) {
    extern __shared__ float smem[];
    float* h_s   = smem;                       // [64][129]
    float* hid_s = smem + FFN_H_S;             // [64][65]
    float* wbuf  = smem + FFN_H_S + FFN_HID_S; // max(w1 chunk [128][64], w2 chunk [64][128])

    int tid = threadIdx.x;
    int rowBase = blockIdx.x * 64;
    int tx = tid & 15, ty = tid >> 4;

    for (int i = tid; i < 64 * 128; i += 256) {
        int r = i >> 7, d = i & 127;
        h_s[r * 129 + d] = g_h[(rowBase + r) * 128 + d];
    }

    float oacc[4][8];
#pragma unroll
    for (int a = 0; a < 4; a++)
#pragma unroll
        for (int b = 0; b < 8; b++) oacc[a][b] = 0.f;

    for (int j = 0; j < 8; j++) {
        __syncthreads();
        // w1 chunk [128][64]
        for (int i = tid; i < 128 * 64; i += 256) {
            int d = i >> 6, hh = i & 63;
            wbuf[d * 64 + hh] = w1[d * 512 + j * 64 + hh];
        }
        __syncthreads();
        // phase A: hid[64][64] = h_s @ w1chunk, micro 4x4
        float ha[4][4];
#pragma unroll
        for (int a = 0; a < 4; a++)
#pragma unroll
            for (int b = 0; b < 4; b++) ha[a][b] = 0.f;
#pragma unroll 8
        for (int kk = 0; kk < 128; kk++) {
            float4 wv = ((const float4*)wbuf)[kk * 16 + tx];
            float a0 = h_s[(ty * 4 + 0) * 129 + kk];
            float a1 = h_s[(ty * 4 + 1) * 129 + kk];
            float a2 = h_s[(ty * 4 + 2) * 129 + kk];
            float a3 = h_s[(ty * 4 + 3) * 129 + kk];
            ha[0][0] += a0 * wv.x; ha[0][1] += a0 * wv.y; ha[0][2] += a0 * wv.z; ha[0][3] += a0 * wv.w;
            ha[1][0] += a1 * wv.x; ha[1][1] += a1 * wv.y; ha[1][2] += a1 * wv.z; ha[1][3] += a1 * wv.w;
            ha[2][0] += a2 * wv.x; ha[2][1] += a2 * wv.y; ha[2][2] += a2 * wv.z; ha[2][3] += a2 * wv.w;
            ha[3][0] += a3 * wv.x; ha[3][1] += a3 * wv.y; ha[3][2] += a3 * wv.z; ha[3][3] += a3 * wv.w;
        }
#pragma unroll
        for (int jj = 0; jj < 4; jj++)
#pragma unroll
            for (int ii = 0; ii < 4; ii++) {
                float v = ha[jj][ii] + b1[j * 64 + tx * 4 + ii];
                hid_s[(ty * 4 + jj) * 65 + tx * 4 + ii] = fmaxf(v, 0.f);
            }
        __syncthreads();
        // w2 chunk [64][128] (reuse wbuf)
        for (int i = tid; i < 64 * 128; i += 256) {
            wbuf[i] = w2[j * 64 * 128 + i];
        }
        __syncthreads();
        // phase B: oacc += hid_s @ w2chunk, micro 4x8
#pragma unroll 4
        for (int kk = 0; kk < 64; kk++) {
            float4 b0 = ((const float4*)wbuf)[kk * 32 + tx * 2];
            float4 b1v = ((const float4*)wbuf)[kk * 32 + tx * 2 + 1];
            float a0 = hid_s[(ty * 4 + 0) * 65 + kk];
            float a1 = hid_s[(ty * 4 + 1) * 65 + kk];
            float a2 = hid_s[(ty * 4 + 2) * 65 + kk];
            float a3 = hid_s[(ty * 4 + 3) * 65 + kk];
            oacc[0][0] += a0 * b0.x; oacc[0][1] += a0 * b0.y; oacc[0][2] += a0 * b0.z; oacc[0][3] += a0 * b0.w;
            oacc[0][4] += a0 * b1v.x; oacc[0][5] += a0 * b1v.y; oacc[0][6] += a0 * b1v.z; oacc[0][7] += a0 * b1v.w;
            oacc[1][0] += a1 * b0.x; oacc[1][1] += a1 * b0.y; oacc[1][2] += a1 * b0.z; oacc[1][3] += a1 * b0.w;
            oacc[1][4] += a1 * b1v.x; oacc[1][5] += a1 * b1v.y; oacc[1][6] += a1 * b1v.z; oacc[1][7] += a1 * b1v.w;
            oacc[2][0] += a2 * b0.x; oacc[2][1] += a2 * b0.y; oacc[2][2] += a2 * b0.z; oacc[2][3] += a2 * b0.w;
            oacc[2][4] += a2 * b1v.x; oacc[2][5] += a2 * b1v.y; oacc[2][6] += a2 * b1v.z; oacc[2][7] += a2 * b1v.w;
            oacc[3][0] += a3 * b0.x; oacc[3][1] += a3 * b0.y; oacc[3][2] += a3 * b0.z; oacc[3][3] += a3 * b0.w;
            oacc[3][4] += a3 * b1v.x; oacc[3][5] += a3 * b1v.y; oacc[3][6] += a3 * b1v.z; oacc[3][7] += a3 * b1v.w;
        }
    }
    int o0 = tx * 8;
    float bb[8];
#pragma unroll
    for (int i = 0; i < 8; i++) bb[i] = b2[o0 + i];
#pragma unroll
    for (int jj = 0; jj < 4; jj++) {
        int r = rowBase + ty * 4 + jj;
        float4 v0 = make_float4(oacc[jj][0] + bb[0], oacc[jj][1] + bb[1],
                                oacc[jj][2] + bb[2], oacc[jj][3] + bb[3]);
        float4 v1 = make_float4(oacc[jj][4] + bb[4], oacc[jj][5] + bb[5],
                                oacc[jj][6] + bb[6], oacc[jj][7] + bb[7]);
        *((float4*)(out + r * 128 + o0)) = v0;
        *((float4*)(out + r * 128 + o0 + 4)) = v1;
    }
}

// ---------------- launch ----------------
extern "C" void kernel_launch(void* const* d_in, const int* in_sizes, int n_in,
                              void* d_out, int out_size) {
    const float* x   = (const float*)d_in[0];
    const float* fw0 = (const float*)d_in[1];
    const float* fw1 = (const float*)d_in[2];
    const float* w1  = (const float*)d_in[3];
    const float* b1  = (const float*)d_in[4];
    const float* w2  = (const float*)d_in[5];
    const float* b2  = (const float*)d_in[6];
    float* out = (float*)d_out;

    cudaFuncSetAttribute(ffn_k, cudaFuncAttributeMaxDynamicSharedMemorySize, FFN_SMEM);

    build_dft_k<<<64, 256>>>();
    repack_k<<<2048, 256>>>(fw0, 0);
    repack_k<<<2048, 256>>>(fw1, 1);

    // y-axis branch (transform over N)
    fwd_k<<<2048, 256>>>(x, 0);
    mix_k<<<dim3(4, 32, 32), 256>>>(0);
    inv_k<<<2048, 256>>>(0);

    // x-axis branch (transform over M), accumulate into g_h
    fwd_k<<<2048, 256>>>(x, 1);
    mix_k<<<dim3(4, 32, 32), 256>>>(1);
    inv_k<<<2048, 256>>>(1);

    // fused FFN
    ffn_k<<<4096, 256, FFN_SMEM>>>(w1, b1, w2, b2, out);
}

// round 4
// speedup vs baseline: 1.4895x; 1.4895x over previous
#include <cuda_runtime.h>
#include <math.h>

// Problem constants
#define NB 16      // batch
#define MD 128     // M (x spatial)
#define ND 128     // N (y spatial)
#define DD 128     // d_model
#define NMODES 32
#define C2 64      // 2*NMODES
#define HH 512     // FFN hidden

// ---------------- scratch (device globals; no runtime allocation) ----------------
__device__ float g_F[C2 * 128];           // forward DFT rows: [c][y], c=2k+ri
__device__ float g_Binv[128 * C2];        // inverse DFT: [y][c]
__device__ float g_Wy[NMODES * 256 * 256];// packed complex-mix matrices, y-axis
__device__ float g_Wx[NMODES * 256 * 256];// packed complex-mix matrices, x-axis
__device__ float g_xf[NB * MD * C2 * DD]; // forward transform output [batch][c][d]
__device__ float g_md[NB * MD * C2 * DD]; // mixed modes            [batch][c][d]
__device__ float g_h[NB * MD * ND * DD];  // fourier-layer output (xx + xy), [b,m,n,d]

// ---------------- DFT matrix construction ----------------
__global__ void build_dft_k() {
    int idx = blockIdx.x * 256 + threadIdx.x;
    const double invs = 0.08838834764831845;  // 1/sqrt(128)
    if (idx < C2 * 128) {
        int c = idx >> 7, y = idx & 127;
        int k = c >> 1;
        int t = (k * y) & 127;
        double s, co;
        sincospi((double)t / 64.0, &s, &co);
        g_F[idx] = (float)(((c & 1) == 0 ? co : -s) * invs);
    } else if (idx < 2 * C2 * 128) {
        int j = idx - C2 * 128;
        int y = j >> 6, c = j & 63;
        int k = c >> 1;
        int t = (k * y) & 127;
        double s, co;
        sincospi((double)t / 64.0, &s, &co);
        double sc = (k == 0 ? 1.0 : 2.0) * invs;
        float v;
        if ((c & 1) == 0) v = (float)(co * sc);
        else              v = (k == 0) ? 0.0f : (float)(-s * sc);
        g_Binv[y * 64 + c] = v;
    }
}

// ---------------- weight repack ----------------
__global__ void repack_k(const float* __restrict__ fw, int which) {
    float* W = which ? g_Wx : g_Wy;
    int idx = blockIdx.x * 256 + threadIdx.x;
    if (idx >= NMODES * DD * DD) return;
    int k = idx >> 14;
    int d = (idx >> 7) & 127;
    int o = idx & 127;
    float wr = fw[((d * DD + o) * NMODES + k) * 2 + 0];
    float wi = fw[((d * DD + o) * NMODES + k) * 2 + 1];
    float* Wk = W + k * 65536;
    Wk[d * 256 + o]               = wr;
    Wk[d * 256 + 128 + o]         = wi;
    Wk[(128 + d) * 256 + o]       = -wi;
    Wk[(128 + d) * 256 + 128 + o] = wr;
}

// ---------------- forward DFT (batched GEMM 64x128x128) ----------------
__global__ void __launch_bounds__(256) fwd_k(const float* __restrict__ x, int mode) {
    __shared__ float F_s[64 * 128];
    __shared__ float X_s[32 * 128];
    int tid = threadIdx.x;
    int batch = blockIdx.x;
    int aStride, base;
    if (mode == 0) { base = batch * 16384; aStride = 128; }
    else { int b = batch >> 7, n = batch & 127; base = b * 2097152 + n * 128; aStride = 16384; }
    const float* A = x + base;

    for (int i = tid; i < 64 * 128; i += 256) F_s[i] = g_F[i];

    int dgrp = tid & 31;
    int cgrp = tid >> 5;
    int c0 = cgrp * 8;
    float acc[8][4];
#pragma unroll
    for (int a = 0; a < 8; a++)
#pragma unroll
        for (int b = 0; b < 4; b++) acc[a][b] = 0.f;

    for (int y0 = 0; y0 < 128; y0 += 32) {
        __syncthreads();
        for (int i = tid; i < 32 * 32; i += 256) {
            int row = i >> 5, c4 = i & 31;
            ((float4*)X_s)[row * 32 + c4] =
                *((const float4*)(A + (y0 + row) * aStride + c4 * 4));
        }
        __syncthreads();
#pragma unroll 8
        for (int yy = 0; yy < 32; yy++) {
            float4 xv = ((const float4*)X_s)[yy * 32 + dgrp];
#pragma unroll
            for (int cc = 0; cc < 8; cc++) {
                float f = F_s[(c0 + cc) * 128 + y0 + yy];
                acc[cc][0] += f * xv.x;
                acc[cc][1] += f * xv.y;
                acc[cc][2] += f * xv.z;
                acc[cc][3] += f * xv.w;
            }
        }
    }
    float* O = g_xf + batch * 8192;
#pragma unroll
    for (int cc = 0; cc < 8; cc++) {
        ((float4*)O)[(c0 + cc) * 32 + dgrp] =
            make_float4(acc[cc][0], acc[cc][1], acc[cc][2], acc[cc][3]);
    }
}

// ---------------- mode mixing (per-mode GEMM 2048x256x256) ----------------
__global__ void __launch_bounds__(256) mix_k(int which) {
    __shared__ float A_s[64 * 65];
    __shared__ float B_s[64 * 64];
    const float* W = which ? g_Wx : g_Wy;
    int tid = threadIdx.x;
    int colBase = blockIdx.x * 64;
    int rowBase = blockIdx.y * 64;
    int k = blockIdx.z;
    const float* Wk = W + k * 65536;
    int tx = tid & 15, ty = tid >> 4;
    float acc[4][4];
#pragma unroll
    for (int a = 0; a < 4; a++)
#pragma unroll
        for (int b = 0; b < 4; b++) acc[a][b] = 0.f;

    for (int kc0 = 0; kc0 < 256; kc0 += 64) {
        __syncthreads();
        for (int i = tid; i < 4096; i += 256) {
            int r = i >> 6, c = i & 63;
            A_s[r * 65 + c] = g_xf[(rowBase + r) * 8192 + k * 256 + kc0 + c];
            B_s[r * 64 + c] = Wk[(kc0 + r) * 256 + colBase + c];
        }
        __syncthreads();
#pragma unroll 8
        for (int kk = 0; kk < 64; kk++) {
            float4 bv = ((const float4*)B_s)[kk * 16 + tx];
            float a0 = A_s[(ty * 4 + 0) * 65 + kk];
            float a1 = A_s[(ty * 4 + 1) * 65 + kk];
            float a2 = A_s[(ty * 4 + 2) * 65 + kk];
            float a3 = A_s[(ty * 4 + 3) * 65 + kk];
            acc[0][0] += a0 * bv.x; acc[0][1] += a0 * bv.y; acc[0][2] += a0 * bv.z; acc[0][3] += a0 * bv.w;
            acc[1][0] += a1 * bv.x; acc[1][1] += a1 * bv.y; acc[1][2] += a1 * bv.z; acc[1][3] += a1 * bv.w;
            acc[2][0] += a2 * bv.x; acc[2][1] += a2 * bv.y; acc[2][2] += a2 * bv.z; acc[2][3] += a2 * bv.w;
            acc[3][0] += a3 * bv.x; acc[3][1] += a3 * bv.y; acc[3][2] += a3 * bv.z; acc[3][3] += a3 * bv.w;
        }
    }
#pragma unroll
    for (int j = 0; j < 4; j++) {
        float4* mp = (float4*)(g_md + (rowBase + ty * 4 + j) * 8192 + k * 256 + colBase);
        mp[tx] = make_float4(acc[j][0], acc[j][1], acc[j][2], acc[j][3]);
    }
}

// ---------------- inverse DFT + write/accumulate (batched GEMM 128x128x64) ----------------
__global__ void __launch_bounds__(256) inv_k(int mode) {
    __shared__ float Bi_s[128 * 33];
    __shared__ float M_s[32 * 128];
    int tid = threadIdx.x;
    int batch = blockIdx.x;
    int base, ostride;
    if (mode == 0) { base = batch * 16384; ostride = 128; }
    else { int b = batch >> 7, n = batch & 127; base = b * 2097152 + n * 128; ostride = 16384; }
    int tx = tid & 15, ty = tid >> 4;
    int o0 = tx * 8, y0 = ty * 8;
    float acc[8][8];
#pragma unroll
    for (int a = 0; a < 8; a++)
#pragma unroll
        for (int b = 0; b < 8; b++) acc[a][b] = 0.f;

    for (int kc0 = 0; kc0 < 64; kc0 += 32) {
        __syncthreads();
        for (int i = tid; i < 128 * 32; i += 256) {
            int y = i >> 5, c = i & 31;
            Bi_s[y * 33 + c] = g_Binv[y * 64 + kc0 + c];
        }
        for (int i = tid; i < 32 * 128; i += 256) {
            int r = i >> 7, o = i & 127;
            M_s[i] = g_md[batch * 8192 + (kc0 + r) * 128 + o];
        }
        __syncthreads();
#pragma unroll 4
        for (int kk = 0; kk < 32; kk++) {
            float a[8];
#pragma unroll
            for (int j = 0; j < 8; j++) a[j] = Bi_s[(y0 + j) * 33 + kk];
            float4 b0 = ((const float4*)M_s)[kk * 32 + tx * 2];
            float4 b1 = ((const float4*)M_s)[kk * 32 + tx * 2 + 1];
#pragma unroll
            for (int j = 0; j < 8; j++) {
                acc[j][0] += a[j] * b0.x; acc[j][1] += a[j] * b0.y;
                acc[j][2] += a[j] * b0.z; acc[j][3] += a[j] * b0.w;
                acc[j][4] += a[j] * b1.x; acc[j][5] += a[j] * b1.y;
                acc[j][6] += a[j] * b1.z; acc[j][7] += a[j] * b1.w;
            }
        }
    }
#pragma unroll
    for (int j = 0; j < 8; j++) {
        float* p = g_h + base + (y0 + j) * ostride + o0;
        float4 v0 = make_float4(acc[j][0], acc[j][1], acc[j][2], acc[j][3]);
        float4 v1 = make_float4(acc[j][4], acc[j][5], acc[j][6], acc[j][7]);
        if (mode == 1) {
            float4 o0v = *((float4*)p);
            float4 o1v = *((float4*)(p + 4));
            v0.x += o0v.x; v0.y += o0v.y; v0.z += o0v.z; v0.w += o0v.w;
            v1.x += o1v.x; v1.y += o1v.y; v1.z += o1v.z; v1.w += o1v.w;
        }
        *((float4*)p) = v0;
        *((float4*)(p + 4)) = v1;
    }
}

// ---------------- TF32 helpers ----------------
__device__ __forceinline__ unsigned f2tf(float x) {
    unsigned r;
    asm("cvt.rna.tf32.f32 %0, %1;" : "=r"(r) : "f"(x));
    return r;
}

__device__ __forceinline__ void mma_tf32(float c[4],
                                         unsigned a0, unsigned a1, unsigned a2, unsigned a3,
                                         unsigned b0, unsigned b1) {
    asm("mma.sync.aligned.m16n8k8.row.col.f32.tf32.tf32.f32 "
        "{%0,%1,%2,%3}, {%4,%5,%6,%7}, {%8,%9}, {%0,%1,%2,%3};"
        : "+f"(c[0]), "+f"(c[1]), "+f"(c[2]), "+f"(c[3])
        : "r"(a0), "r"(a1), "r"(a2), "r"(a3), "r"(b0), "r"(b1));
}

// ---------------- fused FFN via TF32 tensor-core MMA ----------------
// out = relu(h @ w1 + b1) @ w2 + b2, 128-row tile per block, H chunked by 64.
// smem pitches chosen so pitch % 32 == 4 -> conflict-free fragment LDS.
#define FP_H   132   // h_s   [128][132]
#define FP_W1  68    // w1c   [128][68]  (chunk n=64)
#define FP_HID 68    // hid_s [128][68]  (chunk n=64)
#define FP_W2  132   // w2c   [64][132]
#define FFN2_SMEM ((128*FP_H + 128*FP_W1 + 128*FP_HID + 64*FP_W2) * 4)

__global__ void __launch_bounds__(256, 1) ffn_mma_k(const float* __restrict__ w1,
                                                    const float* __restrict__ b1,
                                                    const float* __restrict__ w2,
                                                    const float* __restrict__ b2,
                                                    float* __restrict__ out) {
    extern __shared__ unsigned smem_u[];
    unsigned* h_s   = smem_u;                       // tf32 bits
    unsigned* w1c   = h_s + 128 * FP_H;
    unsigned* hid_s = w1c + 128 * FP_W1;
    unsigned* w2c   = hid_s + 128 * FP_HID;

    int tid = threadIdx.x;
    int warp = tid >> 5, lane = tid & 31;
    int gid = lane >> 2, tig = lane & 3;   // groupID, thread-in-group
    int rowBase = blockIdx.x * 128;
    int r0 = warp * 16;                    // warp row offset in tile

    // stage h tile -> tf32
    for (int i = tid; i < 128 * 128; i += 256) {
        int r = i >> 7, d = i & 127;
        h_s[r * FP_H + d] = f2tf(g_h[(rowBase + r) * 128 + d]);
    }

    float oacc[16][4];
#pragma unroll
    for (int t = 0; t < 16; t++)
#pragma unroll
        for (int c = 0; c < 4; c++) oacc[t][c] = 0.f;

    for (int j = 0; j < 8; j++) {
        __syncthreads();   // also covers initial h_s staging
        // stage w1 chunk [k=128][n=64] -> tf32
        for (int i = tid; i < 128 * 64; i += 256) {
            int k = i >> 6, n = i & 63;
            w1c[k * FP_W1 + n] = f2tf(w1[k * 512 + j * 64 + n]);
        }
        __syncthreads();

        // phase A: hid[16][64] per warp = h_s[16][128] @ w1c[128][64]
        float ha[8][4];
#pragma unroll
        for (int t = 0; t < 8; t++)
#pragma unroll
            for (int c = 0; c < 4; c++) ha[t][c] = 0.f;

#pragma unroll
        for (int k0 = 0; k0 < 128; k0 += 8) {
            unsigned a0 = h_s[(r0 + gid) * FP_H + k0 + tig];
            unsigned a1 = h_s[(r0 + gid + 8) * FP_H + k0 + tig];
            unsigned a2 = h_s[(r0 + gid) * FP_H + k0 + tig + 4];
            unsigned a3 = h_s[(r0 + gid + 8) * FP_H + k0 + tig + 4];
#pragma unroll
            for (int nt = 0; nt < 8; nt++) {
                unsigned b0 = w1c[(k0 + tig) * FP_W1 + nt * 8 + gid];
                unsigned b1r = w1c[(k0 + tig + 4) * FP_W1 + nt * 8 + gid];
                mma_tf32(ha[nt], a0, a1, a2, a3, b0, b1r);
            }
        }
        // epilogue A: bias + relu, store hid as tf32
#pragma unroll
        for (int nt = 0; nt < 8; nt++) {
            int n = nt * 8 + tig * 2;
            float bb0 = b1[j * 64 + n];
            float bb1 = b1[j * 64 + n + 1];
            hid_s[(r0 + gid) * FP_HID + n]       = f2tf(fmaxf(ha[nt][0] + bb0, 0.f));
            hid_s[(r0 + gid) * FP_HID + n + 1]   = f2tf(fmaxf(ha[nt][1] + bb1, 0.f));
            hid_s[(r0 + gid + 8) * FP_HID + n]   = f2tf(fmaxf(ha[nt][2] + bb0, 0.f));
            hid_s[(r0 + gid + 8) * FP_HID + n + 1] = f2tf(fmaxf(ha[nt][3] + bb1, 0.f));
        }
        __syncthreads();
        // stage w2 chunk [k=64][n=128] -> tf32
        for (int i = tid; i < 64 * 128; i += 256) {
            int k = i >> 7, n = i & 127;
            w2c[k * FP_W2 + n] = f2tf(w2[(j * 64 + k) * 128 + n]);
        }
        __syncthreads();

        // phase B: oacc[16][128] += hid[16][64] @ w2c[64][128]
#pragma unroll
        for (int k0 = 0; k0 < 64; k0 += 8) {
            unsigned a0 = hid_s[(r0 + gid) * FP_HID + k0 + tig];
            unsigned a1 = hid_s[(r0 + gid + 8) * FP_HID + k0 + tig];
            unsigned a2 = hid_s[(r0 + gid) * FP_HID + k0 + tig + 4];
            unsigned a3 = hid_s[(r0 + gid + 8) * FP_HID + k0 + tig + 4];
#pragma unroll
            for (int nt = 0; nt < 16; nt++) {
                unsigned b0 = w2c[(k0 + tig) * FP_W2 + nt * 8 + gid];
                unsigned b1r = w2c[(k0 + tig + 4) * FP_W2 + nt * 8 + gid];
                mma_tf32(oacc[nt], a0, a1, a2, a3, b0, b1r);
            }
        }
    }

    // final: + b2, store
#pragma unroll
    for (int nt = 0; nt < 16; nt++) {
        int n = nt * 8 + tig * 2;
        float bb0 = b2[n], bb1 = b2[n + 1];
        int r = rowBase + r0 + gid;
        *((float2*)(out + (size_t)r * 128 + n)) =
            make_float2(oacc[nt][0] + bb0, oacc[nt][1] + bb1);
        *((float2*)(out + (size_t)(r + 8) * 128 + n)) =
            make_float2(oacc[nt][2] + bb0, oacc[nt][3] + bb1);
    }
}

// ---------------- launch ----------------
extern "C" void kernel_launch(void* const* d_in, const int* in_sizes, int n_in,
                              void* d_out, int out_size) {
    const float* x   = (const float*)d_in[0];
    const float* fw0 = (const float*)d_in[1];
    const float* fw1 = (const float*)d_in[2];
    const float* w1  = (const float*)d_in[3];
    const float* b1  = (const float*)d_in[4];
    const float* w2  = (const float*)d_in[5];
    const float* b2  = (const float*)d_in[6];
    float* out = (float*)d_out;

    cudaFuncSetAttribute(ffn_mma_k, cudaFuncAttributeMaxDynamicSharedMemorySize, FFN2_SMEM);

    build_dft_k<<<64, 256>>>();
    repack_k<<<2048, 256>>>(fw0, 0);
    repack_k<<<2048, 256>>>(fw1, 1);

    // y-axis branch (transform over N)
    fwd_k<<<2048, 256>>>(x, 0);
    mix_k<<<dim3(4, 32, 32), 256>>>(0);
    inv_k<<<2048, 256>>>(0);

    // x-axis branch (transform over M), accumulate into g_h
    fwd_k<<<2048, 256>>>(x, 1);
    mix_k<<<dim3(4, 32, 32), 256>>>(1);
    inv_k<<<2048, 256>>>(1);

    // fused FFN on tensor cores (TF32)
    ffn_mma_k<<<2048, 256, FFN2_SMEM>>>(w1, b1, w2, b2, out);
}